// round 16
// baseline (speedup 1.0000x reference)
#include <cuda_runtime.h>
#include <math.h>

// Problem constants
#define Bb   16
#define Tt   32
#define Ss   128
#define Ff   3
#define Hh   256
#define NHh  8
#define DKk  32
#define TPp  4
#define BSr  2048            // B*S rows
#define KENC 528             // padded 3+256+256=515 -> 528
#define KDEC 768             // 256+256+256
#define NG   1024            // 4*H

// ---------------- device state / scratch (no allocations allowed) ----------------
__device__ float g_eh[BSr * Hh];
__device__ float g_ec[BSr * Hh];
__device__ float g_dh[BSr * Hh];
__device__ float g_q[BSr * Hh];
__device__ float g_k[BSr * Hh];
__device__ float g_v[BSr * Hh];
__device__ float g_code[BSr * Hh];
__device__ float g_zin[BSr * KDEC];      // concat input (enc ld=528, dec ld=768)
__device__ float g_wgpad[KENC * NG];     // zero-padded + column-permuted enc gate W
__device__ float g_wgdec[KDEC * NG];     // column-permuted dec gate W
__device__ float g_bgenc[NG];            // permuted enc gate bias
__device__ float g_bgdec[NG];            // permuted dec gate bias

// grid barrier state (self-cleaning; replay-safe)
__device__ unsigned g_barcnt = 0;
__device__ volatile unsigned g_bargen = 0;

__device__ __forceinline__ float sigf(float x) { return 1.f / (1.f + expf(-x)); }

__device__ __forceinline__ void grid_bar(int nb)
{
    __threadfence();                 // publish this thread's writes (gpu scope)
    __syncthreads();
    if (threadIdx.x == 0) {
        unsigned gen = g_bargen;
        if (atomicAdd(&g_barcnt, 1u) == (unsigned)nb - 1u) {
            g_barcnt = 0;            // all arrived; safe to reset
            __threadfence();
            g_bargen = gen + 1u;     // release
        } else {
            while (g_bargen == gen) { }
        }
    }
    __syncthreads();
    __threadfence();                 // acquire: invalidate L1 before next phase reads
}

// ---------------- prep: reset state, build permuted weights ----------------
// Permutation: new col p = 4*j + gate  <-> orig col = gate*256 + j.
__global__ void prep_kernel(const float* __restrict__ encWg, const float* __restrict__ decWg,
                            const float* __restrict__ encbg, const float* __restrict__ decbg)
{
    int idx = blockIdx.x * blockDim.x + threadIdx.x;
    int stride = gridDim.x * blockDim.x;
    for (int i = idx; i < BSr * Hh; i += stride) {
        g_eh[i] = 0.f; g_ec[i] = 0.f; g_dh[i] = 0.f;
    }
    for (int i = idx; i < KENC * NG; i += stride) {
        int r = i >> 10, p = i & 1023;
        int oc = ((p & 3) << 8) | (p >> 2);
        g_wgpad[i] = (r < 515) ? encWg[r * 1024 + oc] : 0.f;
    }
    for (int i = idx; i < KDEC * NG; i += stride) {
        int r = i >> 10, p = i & 1023;
        int oc = ((p & 3) << 8) | (p >> 2);
        g_wgdec[i] = decWg[r * 1024 + oc];
    }
    for (int i = idx; i < NG; i += stride) {
        int oc = ((i & 3) << 8) | (i >> 2);
        g_bgenc[i] = encbg[oc];
        g_bgdec[i] = decbg[oc];
    }
}

// ---- fp32 GEMM tile (R14-verified shape): BM=128, BN=64, BK=16, 8x4 microtile ----
// mode 0: plain; 2: sigmoid(x+bias); 3: LSTM write c&h; 4: LSTM write h only
__device__ __forceinline__ void gemm_tile(
    const float* __restrict__ A, const float* __restrict__ W,
    float* __restrict__ C, int K, int N,
    const float* __restrict__ bias, int mode,
    float* __restrict__ Cst, float* __restrict__ Hst,
    int bx, int by, float* sA, float* sB)
{
    const int tid = threadIdx.x;
    const int m0  = by * 128;
    const int n0  = bx * 64;

    const int ar  = tid >> 2;
    const int ac  = (tid & 3) << 2;
    const int br  = tid >> 4;
    const int bc  = (tid & 15) << 2;
    const int tx  = tid & 15;
    const int ty  = tid >> 4;

    const float* aptr0 = A + (long)(m0 + ar) * K + ac;
    const float* aptr1 = A + (long)(m0 + ar + 64) * K + ac;
    const float* bptr  = W + (long)br * N + n0 + bc;

    float acc[8][4];
    #pragma unroll
    for (int i = 0; i < 8; i++)
        #pragma unroll
        for (int j = 0; j < 4; j++) acc[i][j] = 0.f;

    const int nk = K >> 4;

    float4 pa0 = *(const float4*)(aptr0);
    float4 pa1 = *(const float4*)(aptr1);
    float4 pb  = *(const float4*)(bptr);
    {
        float* as = sA;                       // stage 0
        as[(ac + 0) * 132 + ar] = pa0.x;
        as[(ac + 1) * 132 + ar] = pa0.y;
        as[(ac + 2) * 132 + ar] = pa0.z;
        as[(ac + 3) * 132 + ar] = pa0.w;
        as[(ac + 0) * 132 + ar + 64] = pa1.x;
        as[(ac + 1) * 132 + ar + 64] = pa1.y;
        as[(ac + 2) * 132 + ar + 64] = pa1.z;
        as[(ac + 3) * 132 + ar + 64] = pa1.w;
        *(float4*)&sB[br * 64 + bc] = pb;
    }
    __syncthreads();

    for (int t = 0; t < nk; t++) {
        const int cur = t & 1;
        if (t + 1 < nk) {
            int k0 = (t + 1) << 4;
            pa0 = *(const float4*)(aptr0 + k0);
            pa1 = *(const float4*)(aptr1 + k0);
            pb  = *(const float4*)(bptr + (long)k0 * N);
        }
        const float4* asr = (const float4*)(sA + cur * 2112);
        const float4* bsr = (const float4*)(sB + cur * 1024);
        #pragma unroll
        for (int kk = 0; kk < 16; kk++) {
            float4 aA = asr[kk * 33 + ty * 2];
            float4 aB = asr[kk * 33 + ty * 2 + 1];
            float4 bb = bsr[kk * 16 + tx];
            float a[8] = {aA.x, aA.y, aA.z, aA.w, aB.x, aB.y, aB.z, aB.w};
            float b[4] = {bb.x, bb.y, bb.z, bb.w};
            #pragma unroll
            for (int i = 0; i < 8; i++)
                #pragma unroll
                for (int j = 0; j < 4; j++)
                    acc[i][j] = fmaf(a[i], b[j], acc[i][j]);
        }
        if (t + 1 < nk) {
            const int nxt = cur ^ 1;
            float* as = sA + nxt * 2112;
            as[(ac + 0) * 132 + ar] = pa0.x;
            as[(ac + 1) * 132 + ar] = pa0.y;
            as[(ac + 2) * 132 + ar] = pa0.z;
            as[(ac + 3) * 132 + ar] = pa0.w;
            as[(ac + 0) * 132 + ar + 64] = pa1.x;
            as[(ac + 1) * 132 + ar + 64] = pa1.y;
            as[(ac + 2) * 132 + ar + 64] = pa1.z;
            as[(ac + 3) * 132 + ar + 64] = pa1.w;
            *(float4*)&sB[nxt * 1024 + br * 64 + bc] = pb;
        }
        __syncthreads();
    }

    if (mode <= 2) {
        float4 bv = make_float4(0.f, 0.f, 0.f, 0.f);
        if (mode >= 1) bv = *(const float4*)(bias + n0 + (tx << 2));
        #pragma unroll
        for (int i = 0; i < 8; i++) {
            int m = m0 + ty * 8 + i;
            float4 v = make_float4(acc[i][0], acc[i][1], acc[i][2], acc[i][3]);
            if (mode >= 1) { v.x += bv.x; v.y += bv.y; v.z += bv.z; v.w += bv.w; }
            if (mode == 2) { v.x = sigf(v.x); v.y = sigf(v.y); v.z = sigf(v.z); v.w = sigf(v.w); }
            *(float4*)(C + (long)m * N + n0 + (tx << 2)) = v;
        }
    } else {
        float b0 = bias[n0 + (tx << 2) + 0];
        float b1 = bias[n0 + (tx << 2) + 1];
        float b2 = bias[n0 + (tx << 2) + 2];
        float b3 = bias[n0 + (tx << 2) + 3];
        const int hbase = (n0 >> 2) + tx;
        #pragma unroll
        for (int i = 0; i < 8; i++) {
            int m = m0 + ty * 8 + i;
            float zi = acc[i][0] + b0;
            float zf = acc[i][1] + b1;
            float zg = acc[i][2] + b2;
            float zo = acc[i][3] + b3;
            long idx = (long)m * Hh + hbase;
            float c  = Cst[idx];
            float cn = sigf(zf) * c + sigf(zi) * tanhf(zg);
            float hn = sigf(zo) * tanhf(cn);
            if (mode == 3) Cst[idx] = cn;
            Hst[idx] = hn;
        }
    }
    __syncthreads();   // protect smem reuse by next unit/phase
}

// ---------------- attention + concat unit (8 rows) ----------------
__device__ __forceinline__ void attn_unit(
    const float* __restrict__ Q, const float* __restrict__ Km, const float* __restrict__ Vm,
    const float* __restrict__ Hs, const float* __restrict__ Xs,
    int xmode, int t, float* __restrict__ Z, int ldz, int xlen, int unit)
{
    const int row0 = unit << 3;
    const int tid = threadIdx.x;

    if (tid < 64) {
        const int row  = row0 + (tid >> 3);
        const int head = tid & 7;
        const int b = row >> 7;
        const int s = row & 127;
        const float* qp = Q + (long)row * Hh + head * DKk;
        float qv[DKk];
        #pragma unroll
        for (int d = 0; d < DKk; d++) qv[d] = qp[d];

        const int offs[4] = {2, 1, -1, -2};
        float sc[4];
        #pragma unroll
        for (int j = 0; j < 4; j++) {
            int sn = s + offs[j];
            float a = 0.f;
            if (sn >= 0 && sn < Ss) {
                const float* kp = Km + (long)(b * Ss + sn) * Hh + head * DKk;
                #pragma unroll
                for (int d = 0; d < DKk; d++) a = fmaf(qv[d], kp[d], a);
            }
            sc[j] = a * 0.17677669529663687f;
        }
        float mx = fmaxf(fmaxf(sc[0], sc[1]), fmaxf(sc[2], sc[3]));
        float e[4], ssum = 0.f;
        #pragma unroll
        for (int j = 0; j < 4; j++) { e[j] = expf(sc[j] - mx); ssum += e[j]; }
        float inv = 1.f / ssum;

        float ctx[DKk];
        #pragma unroll
        for (int d = 0; d < DKk; d++) ctx[d] = 0.f;
        #pragma unroll
        for (int j = 0; j < 4; j++) {
            int sn = s + offs[j];
            if (sn >= 0 && sn < Ss) {
                const float* vp = Vm + (long)(b * Ss + sn) * Hh + head * DKk;
                float w = e[j] * inv;
                #pragma unroll
                for (int d = 0; d < DKk; d++) ctx[d] = fmaf(w, vp[d], ctx[d]);
            }
        }
        float* zp = Z + (long)row * ldz + xlen + Hh + head * DKk;
        #pragma unroll
        for (int d = 0; d < DKk; d++) zp[d] = ctx[d];
    }

    for (int i = tid; i < 8 * Hh; i += 256) {
        int r = row0 + (i >> 8);
        int c = i & 255;
        Z[(long)r * ldz + xlen + c] = Hs[(long)r * Hh + c];
    }
    if (xmode == 0) {
        for (int i = tid; i < 8 * Ff; i += 256) {
            int r = row0 + i / Ff;
            int f = i - (i / Ff) * Ff;
            int b = r >> 7, s = r & 127;
            Z[(long)r * ldz + f] = Xs[(((long)b * Tt + t) * Ss + s) * Ff + f];
        }
    } else {
        for (int i = tid; i < 8 * Hh; i += 256) {
            int r = row0 + (i >> 8);
            int c = i & 255;
            Z[(long)r * ldz + c] = Xs[(long)r * Hh + c];
        }
    }
}

// ---------------- output head unit (one batch) ----------------
__device__ __forceinline__ void out_unit(
    const float* __restrict__ Dh, const float* __restrict__ outW,
    const float* __restrict__ outB, const float* __restrict__ inp,
    int t, float* __restrict__ Out, int b, float* osh)
{
    int tid = threadIdx.x;
    float o = 0.f;
    if (tid < Ss) {
        int s = tid;
        const float* hp = Dh + (long)(b * Ss + s) * Hh;
        float acc = 0.f;
        #pragma unroll 8
        for (int d = 0; d < Hh; d++) acc = fmaf(hp[d], outW[d], acc);
        o = acc + outB[0];
        osh[s] = o;
    }
    __syncthreads();
    if (tid < Ss) {
        int s = tid;
        float In  = (s == 0) ? inp[(((long)b * Tt + (t + 1)) * Ss + 0) * Ff + 1] : osh[s - 1];
        float num = inp[(((long)b * Tt + t) * Ss + s) * Ff + 2] + In - o;
        if (t >= TPp) {
            float* op = Out + (((long)b * (Tt - 1 - TPp) + (t - TPp)) * Ss + s) * 3;
            op[0] = o; op[1] = In; op[2] = num;
        }
    }
    __syncthreads();
}

// ---------------- persistent megakernel: whole T-loop, one launch ----------------
__global__ void __launch_bounds__(256, 2) mega_kernel(
    const float* __restrict__ input,
    const float* __restrict__ encWq, const float* __restrict__ encWk, const float* __restrict__ encWv,
    const float* __restrict__ decWq, const float* __restrict__ decWk, const float* __restrict__ decWv,
    const float* __restrict__ embW, const float* __restrict__ embb,
    const float* __restrict__ outW, const float* __restrict__ outB,
    float* __restrict__ out, int nb)
{
    __shared__ float sA[2 * 16 * 132];
    __shared__ float sB[2 * 16 * 64];
    __shared__ float osh[Ss];
    const int bid = blockIdx.x;

    for (int t = 0; t < Tt - 1; t++) {
        // P1: enc qkv (192 units)
        for (int u = bid; u < 192; u += nb) {
            int z = u >> 6, r = u & 63, by = r >> 2, bx = r & 3;
            const float* W = (z == 0) ? encWq : ((z == 1) ? encWk : encWv);
            float* C = (z == 0) ? g_q : ((z == 1) ? g_k : g_v);
            gemm_tile(g_eh, W, C, Hh, Hh, 0, 0, 0, 0, bx, by, sA, sB);
        }
        grid_bar(nb);
        // P2: enc attn (256 units)
        for (int u = bid; u < 256; u += nb)
            attn_unit(g_q, g_k, g_v, g_eh, input, 0, t, g_zin, KENC, Ff, u);
        grid_bar(nb);
        // P3: enc gate GEMM + fused LSTM (256 units)
        for (int u = bid; u < 256; u += nb) {
            int by = u >> 4, bx = u & 15;
            gemm_tile(g_zin, g_wgpad, 0, KENC, NG, g_bgenc, 3, g_ec, g_eh, bx, by, sA, sB);
        }
        grid_bar(nb);
        // P4: dec qkv + emb (256 units)
        for (int u = bid; u < 256; u += nb) {
            int z = u >> 6, r = u & 63, by = r >> 2, bx = r & 3;
            if (z < 3) {
                const float* W = (z == 0) ? decWq : ((z == 1) ? decWk : decWv);
                float* C = (z == 0) ? g_q : ((z == 1) ? g_k : g_v);
                gemm_tile(g_dh, W, C, Hh, Hh, 0, 0, 0, 0, bx, by, sA, sB);
            } else {
                gemm_tile(g_eh, embW, g_code, Hh, Hh, embb, 2, 0, 0, bx, by, sA, sB);
            }
        }
        grid_bar(nb);
        // P5: dec attn (256 units)
        for (int u = bid; u < 256; u += nb)
            attn_unit(g_q, g_k, g_v, g_dh, g_code, 1, t, g_zin, KDEC, Hh, u);
        grid_bar(nb);
        // P6: dec gate GEMM + fused LSTM, h only (256 units)
        for (int u = bid; u < 256; u += nb) {
            int by = u >> 4, bx = u & 15;
            gemm_tile(g_zin, g_wgdec, 0, KDEC, NG, g_bgdec, 4, g_dh, g_dh, bx, by, sA, sB);
        }
        grid_bar(nb);
        // P7: output head (16 units)
        for (int u = bid; u < Bb; u += nb)
            out_unit(g_dh, outW, outB, input, t, out, u, osh);
        grid_bar(nb);
    }
}

// ---------------- host launch ----------------
extern "C" void kernel_launch(void* const* d_in, const int* in_sizes, int n_in,
                              void* d_out, int out_size)
{
    const float* input = (const float*)d_in[0];
    const float* encWq = (const float*)d_in[1];
    const float* encWk = (const float*)d_in[2];
    const float* encWv = (const float*)d_in[3];
    const float* encWg = (const float*)d_in[4];
    const float* encbg = (const float*)d_in[5];
    const float* decWq = (const float*)d_in[6];
    const float* decWk = (const float*)d_in[7];
    const float* decWv = (const float*)d_in[8];
    const float* decWg = (const float*)d_in[9];
    const float* decbg = (const float*)d_in[10];
    const float* embW  = (const float*)d_in[11];
    const float* embb  = (const float*)d_in[12];
    const float* outW  = (const float*)d_in[13];
    const float* outB  = (const float*)d_in[14];
    float* out = (float*)d_out;

    // deadlock-proof grid size: guaranteed co-resident blocks
    int nsm = 148, occ = 1;
    cudaDeviceGetAttribute(&nsm, cudaDevAttrMultiProcessorCount, 0);
    cudaOccupancyMaxActiveBlocksPerMultiprocessor(&occ, mega_kernel, 256, 0);
    if (occ < 1) occ = 1;
    if (occ > 2) occ = 2;
    int nb = nsm * occ;

    prep_kernel<<<256, 256>>>(encWg, decWg, encbg, decbg);
    mega_kernel<<<nb, 256>>>(input, encWq, encWk, encWv,
                             decWq, decWk, decWv, embW, embb,
                             outW, outB, out, nb);
}